// round 5
// baseline (speedup 1.0000x reference)
#include <cuda_runtime.h>
#include <math.h>

// ---------------- problem constants ----------------
#define Bn     4
#define Pn     12000
#define Nn     32
#define PNn    (Pn*Nn)            // 384000
#define TOTn   (Bn*PNn)           // 1536000
#define HH     282
#define HW2    (HH*HH)            // 79524
#define OH1    278
#define PH1    139
#define OH2    136
#define PH2    68
#define FCIN   (16*PH2*PH2)       // 73984

typedef unsigned long long ull;

// ---------------- packed f32x2 helpers (Blackwell FFMA2) ----------------
__device__ __forceinline__ ull pk2(float lo, float hi) {
    ull r;
    asm("mov.b64 %0, {%1, %2};" : "=l"(r) : "f"(lo), "f"(hi));
    return r;
}
__device__ __forceinline__ void upk2(ull v, float& lo, float& hi) {
    asm("mov.b64 {%0, %1}, %2;" : "=f"(lo), "=f"(hi) : "l"(v));
}
__device__ __forceinline__ void ffma2(ull& d, ull a, ull b) {
    asm("fma.rn.f32x2 %0, %1, %2, %0;" : "+l"(d) : "l"(a), "l"(b));
}

// ---------------- scratch (static device memory; no allocs) ----------------
__device__ float  g_canvas[(size_t)Bn*128*HW2];       // 162.9 MB
__device__ float  g_conv1 [(size_t)Bn*64*OH1*OH1];    //  79.1 MB
__device__ float  g_pool1 [(size_t)Bn*64*PH1*PH1];    //  19.8 MB
__device__ float  g_conv2 [(size_t)Bn*16*OH2*OH2];
__device__ float  g_pool2 [(size_t)Bn*16*PH2*PH2];
__device__ float  g_feat  [(size_t)Bn*64*Pn];
__device__ int    g_idx   [Bn*Pn];
__device__ double g_mom   [88];       // [0..43] sweep, [44..87] map
__device__ double g_c1stats[128];     // 64 sums + 64 sumsq
__device__ double g_c2stats[32];      // 16 sums + 16 sumsq
__device__ float  g_weff  [512];      // folded PFN weight 64x8
__device__ float  g_beff  [64];
__device__ float  g_ab1   [128];      // conv1 alpha[64], beta[64]
__device__ float  g_ab2   [32];       // conv2 alpha[16], beta[16]
__device__ float  g_h     [128];      // fc1 out (4,32)

// ---------------- zeroing ----------------
__global__ void zero_stats_kernel() {
    int t = threadIdx.x;
    if (t < 88)  g_mom[t]     = 0.0;
    if (t < 128) g_c1stats[t] = 0.0;
    if (t < 32)  g_c2stats[t] = 0.0;
}

__global__ void zero_canvas_kernel() {
    size_t t = (size_t)blockIdx.x * blockDim.x + threadIdx.x;
    const size_t n4 = ((size_t)Bn*128*HW2) / 4;
    if (t < n4) {
        float4 z = make_float4(0.f, 0.f, 0.f, 0.f);
        ((float4*)g_canvas)[t] = z;
    }
}

// ---------------- PFN: raw-input moments ----------------
__global__ void pfn_mom_kernel(const float* __restrict__ x, int off) {
    float a[44];
#pragma unroll
    for (int k = 0; k < 44; k++) a[k] = 0.f;

    for (int i = blockIdx.x * blockDim.x + threadIdx.x; i < TOTn; i += gridDim.x * blockDim.x) {
        int b = i / PNn, r = i % PNn;
        const float* p = x + (size_t)b * 8 * PNn + r;
        float v[8];
#pragma unroll
        for (int c = 0; c < 8; c++) v[c] = p[(size_t)c * PNn];
#pragma unroll
        for (int c = 0; c < 8; c++) a[c] += v[c];
        int k = 8;
#pragma unroll
        for (int c = 0; c < 8; c++)
#pragma unroll
            for (int c2 = c; c2 < 8; c2++)
                a[k++] += v[c] * v[c2];
    }

    __shared__ double sm[44];
    if (threadIdx.x < 44) sm[threadIdx.x] = 0.0;
    __syncthreads();
    int lane = threadIdx.x & 31;
#pragma unroll
    for (int k = 0; k < 44; k++) {
        float s = a[k];
#pragma unroll
        for (int o = 16; o > 0; o >>= 1) s += __shfl_down_sync(0xffffffffu, s, o);
        if (lane == 0) atomicAdd(&sm[k], (double)s);
    }
    __syncthreads();
    if (threadIdx.x < 44) atomicAdd(&g_mom[off + threadIdx.x], sm[threadIdx.x]);
}

// Fold BN(train stats) into effective weight/bias (streaming; no spills).
__global__ void pfn_fin_kernel(int off,
                               const float* __restrict__ w, const float* __restrict__ bias,
                               const float* __restrict__ g, const float* __restrict__ be) {
    int o = threadIdx.x;
    if (o >= 64) return;
    const double invNT = 1.0 / (double)TOTn;

    double wv[8];
#pragma unroll
    for (int c = 0; c < 8; c++) wv[c] = (double)w[o * 8 + c];
    double bo = (double)bias[o];

    double mu = bo;
#pragma unroll
    for (int c = 0; c < 8; c++) mu += wv[c] * (g_mom[off + c] * invNT);

    double quad = 0.0;
    int k = 8;
#pragma unroll
    for (int c = 0; c < 8; c++)
#pragma unroll
        for (int c2 = c; c2 < 8; c2++) {
            double Mv = g_mom[off + k] * invNT;
            k++;
            double t = wv[c] * wv[c2] * Mv;
            quad += (c == c2) ? t : (2.0 * t);
        }

    double ey2 = bo * bo + 2.0 * bo * (mu - bo) + quad;
    double var = ey2 - mu * mu;
    double alpha = (double)g[o] / sqrt(var + 1e-5);
    double beta  = (double)be[o] - mu * alpha;
#pragma unroll
    for (int c = 0; c < 8; c++) g_weff[o * 8 + c] = (float)(alpha * wv[c]);
    g_beff[o] = (float)(alpha * bo + beta);
}

// PFN pass 2: per-(b,p) warp; fused matvec + ReLU + warp-max + grid index.
__global__ void pfn_max_kernel(const float* __restrict__ x) {
    __shared__ float swf[512];
    __shared__ float sbf[64];
    int tid = threadIdx.x;
    for (int i = tid; i < 512; i += 256) swf[i] = g_weff[i];
    if (tid < 64) sbf[tid] = g_beff[tid];
    __syncthreads();

    int warp = (blockIdx.x * 256 + tid) >> 5;
    int lane = tid & 31;
    if (warp >= Bn * Pn) return;
    int b = warp / Pn, p = warp % Pn;

    const float* xb = x + ((size_t)b * 8 * Pn + p) * Nn + lane;
    float xv[8];
#pragma unroll
    for (int c = 0; c < 8; c++) xv[c] = xb[(size_t)c * PNn];

    if (lane == 0) {
        int gx = (int)floorf((xv[0] + 22.0f) / 0.16f);
        int gy = (int)floorf((xv[1] + 22.0f) / 0.16f);
        g_idx[b * Pn + p] = gx * HH + gy;
    }

    for (int o = 0; o < 64; o++) {
        float y = sbf[o];
#pragma unroll
        for (int c = 0; c < 8; c++) y = fmaf(swf[o * 8 + c], xv[c], y);
        y = fmaxf(y, 0.f);
#pragma unroll
        for (int off = 16; off > 0; off >>= 1) y = fmaxf(y, __shfl_xor_sync(0xffffffffu, y, off));
        if (lane == 0) g_feat[((size_t)b * 64 + o) * Pn + p] = y;
    }
}

__global__ void scatter_kernel(int cbase) {
    int t = blockIdx.x * 256 + threadIdx.x;
    if (t >= Bn * 64 * Pn) return;
    int p  = t % Pn;
    int bo = t / Pn;
    int b  = bo >> 6;
    int o  = bo & 63;
    float v = g_feat[t];
    int idx = g_idx[b * Pn + p];
    g_canvas[((size_t)(b * 128 + cbase + o)) * HW2 + idx] = v;
}

// ---------------- conv1: 5x5, 128->64, tile 32x64, 8 oc/block ----------------
// FFMA2 (fma.rn.f32x2) mainloop + register-prefetch ping-pong pipeline.
// Thread = 2 rows x 4 cols of output = 4 f32x2 accumulators per oc.
#define C1_ELEMS (36*68)   // 2448 smem tile elements per channel
__global__ __launch_bounds__(256) void conv1_kernel(const float* __restrict__ wc1,
                                                    const float* __restrict__ bc1) {
    __shared__ float sp[2][36][72];       // padded rows (288B: float4-aligned)
    __shared__ ull   swd[2][200];         // weights pre-duplicated (w,w)
    __shared__ double ssum[8], ssq[8];

    int tid = threadIdx.x;
    int b   = blockIdx.z >> 3, ocg = blockIdx.z & 7;
    int oy  = blockIdx.y * 32, ox = blockIdx.x * 64;
    if (tid < 8) { ssum[tid] = 0.0; ssq[tid] = 0.0; }

    // precompute fill addressing (ci-invariant)
    int goff[10];   // offset into channel plane, or -1 if OOB/unused
    int soff[10];   // smem linear offset (r*72 + c)
#pragma unroll
    for (int k = 0; k < 10; k++) {
        int i = tid + k * 256;
        goff[k] = -1; soff[k] = 0;
        if (i < C1_ELEMS) {
            int r = i / 68, c = i % 68;
            soff[k] = r * 72 + c;
            int gy = oy + r, gx = ox + c;
            if (gy < HH && gx < HH) goff[k] = gy * HH + gx;
            else goff[k] = -2;   // in-tile but OOB -> store 0
        }
    }
    int widx = -1;
    if (tid < 200) widx = ((ocg * 8 + tid / 25) * 128) * 25 + (tid % 25);

    const float* cb = g_canvas + (size_t)b * 128 * HW2;

    ull acc[8][4];
#pragma unroll
    for (int i = 0; i < 8; i++)
#pragma unroll
        for (int j = 0; j < 4; j++) acc[i][j] = 0ull;

    int r0 = (tid >> 4) * 2, c0 = (tid & 15) * 4;

    float pf[10]; float wpf = 0.f;

    // prologue: stage ci=0
    {
        const float* src = cb;
#pragma unroll
        for (int k = 0; k < 10; k++)
            pf[k] = (goff[k] >= 0) ? src[goff[k]] : 0.f;
        if (widx >= 0) wpf = wc1[widx];
#pragma unroll
        for (int k = 0; k < 10; k++) {
            int i = tid + k * 256;
            if (i < C1_ELEMS) ((float*)sp[0])[soff[k]] = pf[k];
        }
        if (widx >= 0) swd[0][tid] = pk2(wpf, wpf);
    }
    __syncthreads();

    for (int ci = 0; ci < 128; ci++) {
        int cur = ci & 1;

        // prefetch next channel into registers (hidden behind compute)
        if (ci + 1 < 128) {
            const float* src = cb + (size_t)(ci + 1) * HW2;
#pragma unroll
            for (int k = 0; k < 10; k++)
                pf[k] = (goff[k] >= 0) ? src[goff[k]] : 0.f;
            if (widx >= 0) wpf = wc1[widx + (ci + 1) * 25];
        }

        // ---- compute from sp[cur] / swd[cur] ----
        const ull* wv = swd[cur];
#pragma unroll
        for (int ky = 0; ky < 5; ky++) {
            const float* rowL = &sp[cur][r0 + ky][c0];
            const float* rowH = &sp[cur][r0 + ky + 1][c0];
            float4 l0 = *(const float4*)rowL;
            float4 l1 = *(const float4*)(rowL + 4);
            float4 h0 = *(const float4*)rowH;
            float4 h1 = *(const float4*)(rowH + 4);

            ull A0 = pk2(l0.x, l0.y), A1 = pk2(l0.z, l0.w);
            ull A2 = pk2(l1.x, l1.y), A3 = pk2(l1.z, l1.w);
            ull B0 = pk2(l0.y, l0.z), B1 = pk2(l0.w, l1.x), B2 = pk2(l1.y, l1.z);
            ull D0 = pk2(h0.x, h0.y), D1 = pk2(h0.z, h0.w);
            ull D2 = pk2(h1.x, h1.y), D3 = pk2(h1.z, h1.w);
            ull E0 = pk2(h0.y, h0.z), E1 = pk2(h0.w, h1.x), E2 = pk2(h1.y, h1.z);

#pragma unroll
            for (int oc = 0; oc < 8; oc++) {
                const ull* wr = &wv[oc * 25 + ky * 5];
                ull w;
                w = wr[0];
                ffma2(acc[oc][0], A0, w); ffma2(acc[oc][1], A1, w);
                ffma2(acc[oc][2], D0, w); ffma2(acc[oc][3], D1, w);
                w = wr[1];
                ffma2(acc[oc][0], B0, w); ffma2(acc[oc][1], B1, w);
                ffma2(acc[oc][2], E0, w); ffma2(acc[oc][3], E1, w);
                w = wr[2];
                ffma2(acc[oc][0], A1, w); ffma2(acc[oc][1], A2, w);
                ffma2(acc[oc][2], D1, w); ffma2(acc[oc][3], D2, w);
                w = wr[3];
                ffma2(acc[oc][0], B1, w); ffma2(acc[oc][1], B2, w);
                ffma2(acc[oc][2], E1, w); ffma2(acc[oc][3], E2, w);
                w = wr[4];
                ffma2(acc[oc][0], A2, w); ffma2(acc[oc][1], A3, w);
                ffma2(acc[oc][2], D2, w); ffma2(acc[oc][3], D3, w);
            }
        }

        // stage next channel into the other buffer
        if (ci + 1 < 128) {
            int nb = 1 - cur;
#pragma unroll
            for (int k = 0; k < 10; k++) {
                int i = tid + k * 256;
                if (i < C1_ELEMS) ((float*)sp[nb])[soff[k]] = pf[k];
            }
            if (widx >= 0) swd[nb][tid] = pk2(wpf, wpf);
        }
        __syncthreads();
    }

    // ---- epilogue: bias, store, BN stats ----
    int lane = tid & 31;
#pragma unroll
    for (int oc = 0; oc < 8; oc++) {
        float bias = bc1[ocg * 8 + oc];
        float v[8];
        upk2(acc[oc][0], v[0], v[1]); upk2(acc[oc][1], v[2], v[3]);
        upk2(acc[oc][2], v[4], v[5]); upk2(acc[oc][3], v[6], v[7]);
        float s = 0.f, sq = 0.f;
#pragma unroll
        for (int iy = 0; iy < 2; iy++)
#pragma unroll
            for (int ix = 0; ix < 4; ix++) {
                int ro = oy + r0 + iy, co = ox + c0 + ix;
                if (ro < OH1 && co < OH1) {
                    float y = v[iy * 4 + ix] + bias;
                    g_conv1[(((size_t)b * 64 + ocg * 8 + oc) * OH1 + ro) * OH1 + co] = y;
                    s += y; sq += y * y;
                }
            }
#pragma unroll
        for (int off = 16; off > 0; off >>= 1) {
            s  += __shfl_down_sync(0xffffffffu, s,  off);
            sq += __shfl_down_sync(0xffffffffu, sq, off);
        }
        if (lane == 0) { atomicAdd(&ssum[oc], (double)s); atomicAdd(&ssq[oc], (double)sq); }
    }
    __syncthreads();
    if (tid < 8) {
        atomicAdd(&g_c1stats[ocg * 8 + tid],      ssum[tid]);
        atomicAdd(&g_c1stats[64 + ocg * 8 + tid], ssq[tid]);
    }
}

// generic BN finalize -> alpha/beta. which: 1 = conv1 (C=64), 2 = conv2 (C=16)
__global__ void bn_fin_kernel(int which,
                              const float* __restrict__ g, const float* __restrict__ be,
                              double invN) {
    int C = (which == 1) ? 64 : 16;
    const double* stats = (which == 1) ? g_c1stats : g_c2stats;
    float* ab           = (which == 1) ? g_ab1     : g_ab2;
    int c = threadIdx.x;
    if (c >= C) return;
    double mean = stats[c] * invN;
    double var  = stats[C + c] * invN - mean * mean;
    double alpha = (double)g[c] / sqrt(var + 1e-5);
    double beta  = (double)be[c] - mean * alpha;
    ab[c]     = (float)alpha;
    ab[C + c] = (float)beta;
}

__global__ void pool1_kernel() {
    int t = blockIdx.x * 256 + threadIdx.x;
    if (t >= Bn * 64 * PH1 * PH1) return;
    int j = t % PH1; int tmp = t / PH1;
    int i = tmp % PH1; tmp /= PH1;
    int c = tmp % 64;  int b = tmp / 64;
    float a = g_ab1[c], bt = g_ab1[64 + c];
    size_t base = (((size_t)b * 64 + c) * OH1 + 2 * i) * OH1 + 2 * j;
    float v0 = fmaf(a, g_conv1[base],        bt);
    float v1 = fmaf(a, g_conv1[base + 1],    bt);
    float v2 = fmaf(a, g_conv1[base + OH1],  bt);
    float v3 = fmaf(a, g_conv1[base + OH1 + 1], bt);
    float r = fmaxf(fmaxf(v0, v1), fmaxf(v2, v3));
    g_pool1[t] = fmaxf(r, 0.f);
}

// ---------------- conv2: 4x4, 64->16, tile 32x32, 8 oc/block, thread = 2x2 px ----------------
__global__ __launch_bounds__(256) void conv2_kernel(const float* __restrict__ wc2,
                                                    const float* __restrict__ bc2) {
    __shared__ float sp[35][36];
    __shared__ float sw[128];
    __shared__ double ssum[8], ssq[8];
    int tid = threadIdx.x;
    int b   = blockIdx.z >> 1, ocg = blockIdx.z & 1;
    int oy  = blockIdx.y * 32, ox = blockIdx.x * 32;
    if (tid < 8) { ssum[tid] = 0.0; ssq[tid] = 0.0; }

    float acc[8][4];
#pragma unroll
    for (int i = 0; i < 8; i++)
#pragma unroll
        for (int j = 0; j < 4; j++) acc[i][j] = 0.f;

    const float* cb = g_pool1 + (size_t)b * 64 * PH1 * PH1;
    int r0 = (tid >> 4) * 2, c0 = (tid & 15) * 2;

    for (int ci = 0; ci < 64; ci++) {
        __syncthreads();
        const float* src = cb + (size_t)ci * PH1 * PH1;
        for (int i = tid; i < 35 * 35; i += 256) {
            int r = i / 35, c = i % 35;
            int gy = oy + r, gx = ox + c;
            sp[r][c] = (gy < PH1 && gx < PH1) ? src[gy * PH1 + gx] : 0.f;
        }
        if (tid < 128) sw[tid] = wc2[((ocg * 8 + (tid >> 4)) * 64 + ci) * 16 + (tid & 15)];
        __syncthreads();

        float pr[5][5];
#pragma unroll
        for (int i = 0; i < 5; i++)
#pragma unroll
            for (int j = 0; j < 5; j++) pr[i][j] = sp[r0 + i][c0 + j];

#pragma unroll
        for (int oc = 0; oc < 8; oc++)
#pragma unroll
            for (int ky = 0; ky < 4; ky++)
#pragma unroll
                for (int kx = 0; kx < 4; kx++) {
                    float wv = sw[oc * 16 + ky * 4 + kx];
#pragma unroll
                    for (int iy = 0; iy < 2; iy++)
#pragma unroll
                        for (int ix = 0; ix < 2; ix++)
                            acc[oc][iy * 2 + ix] = fmaf(pr[ky + iy][kx + ix], wv, acc[oc][iy * 2 + ix]);
                }
    }

    int lane = tid & 31;
#pragma unroll
    for (int oc = 0; oc < 8; oc++) {
        float bias = bc2[ocg * 8 + oc];
        float s = 0.f, sq = 0.f;
#pragma unroll
        for (int iy = 0; iy < 2; iy++)
#pragma unroll
            for (int ix = 0; ix < 2; ix++) {
                int ro = oy + r0 + iy, co = ox + c0 + ix;
                if (ro < OH2 && co < OH2) {
                    float y = acc[oc][iy * 2 + ix] + bias;
                    g_conv2[(((size_t)b * 16 + ocg * 8 + oc) * OH2 + ro) * OH2 + co] = y;
                    s += y; sq += y * y;
                }
            }
#pragma unroll
        for (int off = 16; off > 0; off >>= 1) {
            s  += __shfl_down_sync(0xffffffffu, s,  off);
            sq += __shfl_down_sync(0xffffffffu, sq, off);
        }
        if (lane == 0) { atomicAdd(&ssum[oc], (double)s); atomicAdd(&ssq[oc], (double)sq); }
    }
    __syncthreads();
    if (tid < 8) {
        atomicAdd(&g_c2stats[ocg * 8 + tid],      ssum[tid]);
        atomicAdd(&g_c2stats[16 + ocg * 8 + tid], ssq[tid]);
    }
}

__global__ void pool2_kernel() {
    int t = blockIdx.x * 256 + threadIdx.x;
    if (t >= Bn * 16 * PH2 * PH2) return;
    int j = t % PH2; int tmp = t / PH2;
    int i = tmp % PH2; tmp /= PH2;
    int c = tmp % 16;  int b = tmp / 16;
    float a = g_ab2[c], bt = g_ab2[16 + c];
    size_t base = (((size_t)b * 16 + c) * OH2 + 2 * i) * OH2 + 2 * j;
    float v0 = fmaf(a, g_conv2[base],            bt);
    float v1 = fmaf(a, g_conv2[base + 1],        bt);
    float v2 = fmaf(a, g_conv2[base + OH2],      bt);
    float v3 = fmaf(a, g_conv2[base + OH2 + 1],  bt);
    float r = fmaxf(fmaxf(v0, v1), fmaxf(v2, v3));
    g_pool2[t] = fmaxf(r, 0.f);
}

// ---------------- fc1 ----------------
__global__ void fc1_kernel(const float* __restrict__ w, const float* __restrict__ bias) {
    int j = blockIdx.x, b = blockIdx.y, tid = threadIdx.x;
    const float* x  = g_pool2 + (size_t)b * FCIN;
    const float* wr = w + (size_t)j * FCIN;
    float s = 0.f;
    for (int i = tid; i < FCIN; i += 256) s = fmaf(x[i], wr[i], s);
    __shared__ float red[256];
    red[tid] = s;
    __syncthreads();
    for (int k = 128; k > 0; k >>= 1) {
        if (tid < k) red[tid] += red[tid + k];
        __syncthreads();
    }
    if (tid == 0) g_h[b * 32 + j] = red[0] + bias[j];
}

// ---------------- head ----------------
__global__ void head_kernel(const float* __restrict__ gfc, const float* __restrict__ befc,
                            const float* __restrict__ wout, const float* __restrict__ bout,
                            float* __restrict__ out) {
    __shared__ float hn[4][32];
    int t = threadIdx.x;
    if (t < 32) {
        float h0 = g_h[t], h1 = g_h[32 + t], h2 = g_h[64 + t], h3 = g_h[96 + t];
        float m = 0.25f * (h0 + h1 + h2 + h3);
        float d0 = h0 - m, d1 = h1 - m, d2 = h2 - m, d3 = h3 - m;
        float v = 0.25f * (d0 * d0 + d1 * d1 + d2 * d2 + d3 * d3);
        float inv = rsqrtf(v + 1e-5f);
        float gg = gfc[t], bb = befc[t];
        hn[0][t] = tanhf(fmaf(d0 * inv, gg, bb));
        hn[1][t] = tanhf(fmaf(d1 * inv, gg, bb));
        hn[2][t] = tanhf(fmaf(d2 * inv, gg, bb));
        hn[3][t] = tanhf(fmaf(d3 * inv, gg, bb));
    }
    __syncthreads();
    if (t < 12) {
        int b = t / 3, k = t % 3;
        float s = bout[k];
#pragma unroll
        for (int j = 0; j < 32; j++) s = fmaf(hn[b][j], wout[k * 32 + j], s);
        out[b * 3 + k] = s;
    }
}

// ---------------- launch ----------------
extern "C" void kernel_launch(void* const* d_in, const int* in_sizes, int n_in,
                              void* d_out, int out_size) {
    const float* sweep   = (const float*)d_in[0];
    const float* map_pts = (const float*)d_in[1];
    const float* w_pfn_s = (const float*)d_in[2];
    const float* b_pfn_s = (const float*)d_in[3];
    const float* g_pfn_s = (const float*)d_in[4];
    const float* be_pfn_s= (const float*)d_in[5];
    const float* w_pfn_m = (const float*)d_in[6];
    const float* b_pfn_m = (const float*)d_in[7];
    const float* g_pfn_m = (const float*)d_in[8];
    const float* be_pfn_m= (const float*)d_in[9];
    const float* w_c1    = (const float*)d_in[10];
    const float* b_c1    = (const float*)d_in[11];
    const float* g_c1    = (const float*)d_in[12];
    const float* be_c1   = (const float*)d_in[13];
    const float* w_c2    = (const float*)d_in[14];
    const float* b_c2    = (const float*)d_in[15];
    const float* g_c2    = (const float*)d_in[16];
    const float* be_c2   = (const float*)d_in[17];
    const float* w_fc1   = (const float*)d_in[18];
    const float* b_fc1   = (const float*)d_in[19];
    const float* g_fc1   = (const float*)d_in[20];
    const float* be_fc1  = (const float*)d_in[21];
    const float* w_out   = (const float*)d_in[22];
    const float* b_out   = (const float*)d_in[23];
    float* out = (float*)d_out;

    zero_stats_kernel<<<1, 128>>>();
    {
        int n4 = (int)(((size_t)Bn * 128 * HW2) / 4);
        zero_canvas_kernel<<<(n4 + 255) / 256, 256>>>();
    }

    pfn_mom_kernel<<<1024, 256>>>(sweep,   0);
    pfn_mom_kernel<<<1024, 256>>>(map_pts, 44);

    pfn_fin_kernel<<<1, 64>>>(0, w_pfn_s, b_pfn_s, g_pfn_s, be_pfn_s);
    pfn_max_kernel<<<(Bn * Pn) / 8, 256>>>(sweep);
    scatter_kernel<<<(Bn * 64 * Pn) / 256, 256>>>(0);

    pfn_fin_kernel<<<1, 64>>>(44, w_pfn_m, b_pfn_m, g_pfn_m, be_pfn_m);
    pfn_max_kernel<<<(Bn * Pn) / 8, 256>>>(map_pts);
    scatter_kernel<<<(Bn * 64 * Pn) / 256, 256>>>(64);

    conv1_kernel<<<dim3(5, 9, 32), 256>>>(w_c1, b_c1);
    bn_fin_kernel<<<1, 64>>>(1, g_c1, be_c1, 1.0 / ((double)Bn * OH1 * OH1));
    pool1_kernel<<<(Bn * 64 * PH1 * PH1 + 255) / 256, 256>>>();

    conv2_kernel<<<dim3(5, 5, 8), 256>>>(w_c2, b_c2);
    bn_fin_kernel<<<1, 32>>>(2, g_c2, be_c2, 1.0 / ((double)Bn * OH2 * OH2));
    pool2_kernel<<<(Bn * 16 * PH2 * PH2) / 256, 256>>>();

    fc1_kernel<<<dim3(32, 4), 256>>>(w_fc1, b_fc1);
    head_kernel<<<1, 64>>>(g_fc1, be_fc1, w_out, b_out, out);
}

// round 6
// speedup vs baseline: 3.4240x; 3.4240x over previous
#include <cuda_runtime.h>
#include <math.h>

// ---------------- problem constants ----------------
#define Bn     4
#define Pn     12000
#define Nn     32
#define PNn    (Pn*Nn)            // 384000
#define TOTn   (Bn*PNn)           // 1536000
#define HH     282
#define OH1    278
#define PH1    139
#define OH2    136
#define PH2    68
#define FCIN   (16*PH2*PH2)       // 73984
#define NPILT  (Bn*Pn)            // 48000 pillar entries per half
#define OSZ1   (OH1*OH1)          // 77284

// ---------------- scratch (static device memory; no allocs) ----------------
__device__ float  g_conv1 [(size_t)Bn*64*OSZ1];       //  79.1 MB
__device__ float  g_pool1 [(size_t)Bn*64*PH1*PH1];    //  19.8 MB
__device__ float  g_conv2 [(size_t)Bn*16*OH2*OH2];
__device__ float  g_pool2 [(size_t)Bn*16*PH2*PH2];
__device__ float  g_featT [(size_t)2*NPILT*64];       // pillar-major PFN features (24.6MB)
__device__ int    g_cxy   [2*NPILT];                  // packed (cy<<16)|cx per pillar
__device__ double g_mom   [88];       // [0..43] sweep, [44..87] map
__device__ double g_c1stats[128];     // 64 sums + 64 sumsq
__device__ double g_c2stats[32];      // 16 sums + 16 sumsq
__device__ float  g_weff  [512];      // folded PFN weight 64x8
__device__ float  g_beff  [64];
__device__ float  g_ab1   [128];      // conv1 alpha[64], beta[64]
__device__ float  g_ab2   [32];       // conv2 alpha[16], beta[16]
__device__ float  g_h     [128];      // fc1 out (4,32)

// ---------------- init ----------------
__global__ void zero_stats_kernel() {
    int t = threadIdx.x;
    if (t < 88)  g_mom[t]     = 0.0;
    if (t < 128) g_c1stats[t] = 0.0;
    if (t < 32)  g_c2stats[t] = 0.0;
}

// conv1 buffer = bias everywhere (scatter accumulates on top)
__global__ void conv1_init_kernel(const float* __restrict__ bc1) {
    int t = blockIdx.x * 256 + threadIdx.x;
    if (t >= OSZ1) return;
    int plane = blockIdx.y;                       // b*64 + oc, 0..255
    g_conv1[(size_t)plane * OSZ1 + t] = bc1[plane & 63];
}

// ---------------- PFN: raw-input moments (both clouds; blockIdx.y selects) ----------------
__global__ void pfn_mom_kernel(const float* __restrict__ xs, const float* __restrict__ xm) {
    const float* x = blockIdx.y ? xm : xs;
    int off = blockIdx.y * 44;
    float a[44];
#pragma unroll
    for (int k = 0; k < 44; k++) a[k] = 0.f;

    for (int i = blockIdx.x * blockDim.x + threadIdx.x; i < TOTn; i += gridDim.x * blockDim.x) {
        int b = i / PNn, r = i % PNn;
        const float* p = x + (size_t)b * 8 * PNn + r;
        float v[8];
#pragma unroll
        for (int c = 0; c < 8; c++) v[c] = p[(size_t)c * PNn];
#pragma unroll
        for (int c = 0; c < 8; c++) a[c] += v[c];
        int k = 8;
#pragma unroll
        for (int c = 0; c < 8; c++)
#pragma unroll
            for (int c2 = c; c2 < 8; c2++)
                a[k++] += v[c] * v[c2];
    }

    __shared__ double sm[44];
    if (threadIdx.x < 44) sm[threadIdx.x] = 0.0;
    __syncthreads();
    int lane = threadIdx.x & 31;
#pragma unroll
    for (int k = 0; k < 44; k++) {
        float s = a[k];
#pragma unroll
        for (int o = 16; o > 0; o >>= 1) s += __shfl_down_sync(0xffffffffu, s, o);
        if (lane == 0) atomicAdd(&sm[k], (double)s);
    }
    __syncthreads();
    if (threadIdx.x < 44) atomicAdd(&g_mom[off + threadIdx.x], sm[threadIdx.x]);
}

// Fold BN(train stats) into effective weight/bias (streaming; no spills).
__global__ void pfn_fin_kernel(int off,
                               const float* __restrict__ w, const float* __restrict__ bias,
                               const float* __restrict__ g, const float* __restrict__ be) {
    int o = threadIdx.x;
    if (o >= 64) return;
    const double invNT = 1.0 / (double)TOTn;

    double wv[8];
#pragma unroll
    for (int c = 0; c < 8; c++) wv[c] = (double)w[o * 8 + c];
    double bo = (double)bias[o];

    double mu = bo;
#pragma unroll
    for (int c = 0; c < 8; c++) mu += wv[c] * (g_mom[off + c] * invNT);

    double quad = 0.0;
    int k = 8;
#pragma unroll
    for (int c = 0; c < 8; c++)
#pragma unroll
        for (int c2 = c; c2 < 8; c2++) {
            double Mv = g_mom[off + k] * invNT;
            k++;
            double t = wv[c] * wv[c2] * Mv;
            quad += (c == c2) ? t : (2.0 * t);
        }

    double ey2 = bo * bo + 2.0 * bo * (mu - bo) + quad;
    double var = ey2 - mu * mu;
    double alpha = (double)g[o] / sqrt(var + 1e-5);
    double beta  = (double)be[o] - mu * alpha;
#pragma unroll
    for (int c = 0; c < 8; c++) g_weff[o * 8 + c] = (float)(alpha * wv[c]);
    g_beff[o] = (float)(alpha * bo + beta);
}

// PFN pass 2: per-(b,p) warp; fused matvec + ReLU + warp-max.
// Writes pillar-major features g_featT[pe][64] and packed cell coords g_cxy[pe].
__global__ void pfn_max_kernel(const float* __restrict__ x, int base) {
    __shared__ float swf[512];
    __shared__ float sbf[64];
    int tid = threadIdx.x;
    for (int i = tid; i < 512; i += 256) swf[i] = g_weff[i];
    if (tid < 64) sbf[tid] = g_beff[tid];
    __syncthreads();

    int warp = (blockIdx.x * 256 + tid) >> 5;
    int lane = tid & 31;
    if (warp >= Bn * Pn) return;
    int b = warp / Pn, p = warp % Pn;
    int pe = base + b * Pn + p;

    const float* xb = x + ((size_t)b * 8 * Pn + p) * Nn + lane;
    float xv[8];
#pragma unroll
    for (int c = 0; c < 8; c++) xv[c] = xb[(size_t)c * PNn];

    if (lane == 0) {
        int gx = (int)floorf((xv[0] + 22.0f) / 0.16f);
        int gy = (int)floorf((xv[1] + 22.0f) / 0.16f);
        g_cxy[pe] = (gx << 16) | gy;     // cy = gx (row), cx = gy (col)
    }

    float yk0 = 0.f, yk1 = 0.f;
    for (int o = 0; o < 64; o++) {
        float y = sbf[o];
#pragma unroll
        for (int c = 0; c < 8; c++) y = fmaf(swf[o * 8 + c], xv[c], y);
        y = fmaxf(y, 0.f);
#pragma unroll
        for (int off = 16; off > 0; off >>= 1) y = fmaxf(y, __shfl_xor_sync(0xffffffffu, y, off));
        if (o == lane)      yk0 = y;
        if (o == lane + 32) yk1 = y;
    }
    g_featT[(size_t)pe * 64 + lane]      = yk0;
    g_featT[(size_t)pe * 64 + 32 + lane] = yk1;
}

// ---------------- sparse scatter conv1 ----------------
// block = (pillar chunk, oc-group of 8, half). thread(<200) = (oc_local, tap).
// 64 weights register-resident; pillar feature broadcast from smem (float4).
// Accumulates into bias-initialized g_conv1 via red.global.add.f32.
#define SC_CHUNKS 25            // chunks per batch -> 480 pillars each
#define SC_PPC    480
#define SC_PB     6             // pillars staged per barrier (480/6 = 80 groups)
__global__ __launch_bounds__(224) void sconv1_kernel(const float* __restrict__ wc1) {
    __shared__ float sf[SC_PB][64];
    __shared__ int scell[SC_PB];
    int t    = threadIdx.x;
    int half = blockIdx.z;
    int ocg  = blockIdx.y;               // 0..7
    int chunk= blockIdx.x;               // 0..99
    int b    = chunk / SC_CHUNKS;
    int sub  = chunk % SC_CHUNKS;
    int pbase = half * NPILT + b * Pn + sub * SC_PPC;

    int ocl = t / 25;                    // 0..7 for t<200
    int pos = t - ocl * 25;
    int dy = pos / 5, dx = pos - dy * 5;
    int oc = ocg * 8 + ocl;

    float w[64];
    if (t < 200) {
        const float* wp = wc1 + ((size_t)oc * 128 + half * 64) * 25 + pos;
#pragma unroll
        for (int ci = 0; ci < 64; ci++) w[ci] = wp[ci * 25];
    }
    float* outp = g_conv1 + (size_t)(b * 64 + oc) * OSZ1;

    for (int gp = 0; gp < SC_PPC / SC_PB; gp++) {
        int p0 = pbase + gp * SC_PB;
        __syncthreads();
        if (t < SC_PB * 16) {
            int pi = t >> 4, q = t & 15;
            ((float4*)sf)[t] = ((const float4*)(g_featT + (size_t)(p0 + pi) * 64))[q];
        }
        if (t < SC_PB) scell[t] = g_cxy[p0 + t];
        __syncthreads();
        if (t < 200) {
            for (int pi = 0; pi < SC_PB; pi++) {
                const float4* fv = (const float4*)sf[pi];
                float y0 = 0.f, y1 = 0.f, y2 = 0.f, y3 = 0.f;
#pragma unroll
                for (int k = 0; k < 16; k++) {
                    float4 f = fv[k];
                    y0 = fmaf(w[4 * k],     f.x, y0);
                    y1 = fmaf(w[4 * k + 1], f.y, y1);
                    y2 = fmaf(w[4 * k + 2], f.z, y2);
                    y3 = fmaf(w[4 * k + 3], f.w, y3);
                }
                float y = (y0 + y1) + (y2 + y3);
                int cxy = scell[pi];
                int oy = (cxy >> 16) - dy;
                int ox = (cxy & 0xFFFF) - dx;
                if ((unsigned)oy < (unsigned)OH1 && (unsigned)ox < (unsigned)OH1)
                    atomicAdd(outp + oy * OH1 + ox, y);   // REDG (no return)
            }
        }
    }
}

// conv1 BN statistics pass (sum/sumsq per channel over the accumulated output)
__global__ void c1stats_kernel() {
    int plane = blockIdx.x;                 // b*64+oc, 0..255
    const float* src = g_conv1 + (size_t)plane * OSZ1;
    float s = 0.f, sq = 0.f;
    for (int i = threadIdx.x; i < OSZ1; i += 256) {
        float v = src[i];
        s += v; sq = fmaf(v, v, sq);
    }
    int lane = threadIdx.x & 31, wid = threadIdx.x >> 5;
#pragma unroll
    for (int o = 16; o > 0; o >>= 1) {
        s  += __shfl_down_sync(0xffffffffu, s,  o);
        sq += __shfl_down_sync(0xffffffffu, sq, o);
    }
    __shared__ float rs[8], rq[8];
    if (lane == 0) { rs[wid] = s; rq[wid] = sq; }
    __syncthreads();
    if (threadIdx.x == 0) {
        double S = 0.0, Q = 0.0;
#pragma unroll
        for (int i = 0; i < 8; i++) { S += (double)rs[i]; Q += (double)rq[i]; }
        atomicAdd(&g_c1stats[plane & 63], S);
        atomicAdd(&g_c1stats[64 + (plane & 63)], Q);
    }
}

// generic BN finalize -> alpha/beta. which: 1 = conv1 (C=64), 2 = conv2 (C=16)
__global__ void bn_fin_kernel(int which,
                              const float* __restrict__ g, const float* __restrict__ be,
                              double invN) {
    int C = (which == 1) ? 64 : 16;
    const double* stats = (which == 1) ? g_c1stats : g_c2stats;
    float* ab           = (which == 1) ? g_ab1     : g_ab2;
    int c = threadIdx.x;
    if (c >= C) return;
    double mean = stats[c] * invN;
    double var  = stats[C + c] * invN - mean * mean;
    double alpha = (double)g[c] / sqrt(var + 1e-5);
    double beta  = (double)be[c] - mean * alpha;
    ab[c]     = (float)alpha;
    ab[C + c] = (float)beta;
}

__global__ void pool1_kernel() {
    int t = blockIdx.x * 256 + threadIdx.x;
    if (t >= Bn * 64 * PH1 * PH1) return;
    int j = t % PH1; int tmp = t / PH1;
    int i = tmp % PH1; tmp /= PH1;
    int c = tmp % 64;  int b = tmp / 64;
    float a = g_ab1[c], bt = g_ab1[64 + c];
    size_t base = (((size_t)b * 64 + c) * OH1 + 2 * i) * OH1 + 2 * j;
    float v0 = fmaf(a, g_conv1[base],           bt);
    float v1 = fmaf(a, g_conv1[base + 1],       bt);
    float v2 = fmaf(a, g_conv1[base + OH1],     bt);
    float v3 = fmaf(a, g_conv1[base + OH1 + 1], bt);
    float r = fmaxf(fmaxf(v0, v1), fmaxf(v2, v3));
    g_pool1[t] = fmaxf(r, 0.f);
}

// ---------------- conv2: 4x4, 64->16, tile 32x32, 8 oc/block, thread = 2x2 px ----------------
__global__ __launch_bounds__(256) void conv2_kernel(const float* __restrict__ wc2,
                                                    const float* __restrict__ bc2) {
    __shared__ float sp[35][36];
    __shared__ float sw[128];
    __shared__ double ssum[8], ssq[8];
    int tid = threadIdx.x;
    int b   = blockIdx.z >> 1, ocg = blockIdx.z & 1;
    int oy  = blockIdx.y * 32, ox = blockIdx.x * 32;
    if (tid < 8) { ssum[tid] = 0.0; ssq[tid] = 0.0; }

    float acc[8][4];
#pragma unroll
    for (int i = 0; i < 8; i++)
#pragma unroll
        for (int j = 0; j < 4; j++) acc[i][j] = 0.f;

    const float* cb = g_pool1 + (size_t)b * 64 * PH1 * PH1;
    int r0 = (tid >> 4) * 2, c0 = (tid & 15) * 2;

    for (int ci = 0; ci < 64; ci++) {
        __syncthreads();
        const float* src = cb + (size_t)ci * PH1 * PH1;
        for (int i = tid; i < 35 * 35; i += 256) {
            int r = i / 35, c = i % 35;
            int gy = oy + r, gx = ox + c;
            sp[r][c] = (gy < PH1 && gx < PH1) ? src[gy * PH1 + gx] : 0.f;
        }
        if (tid < 128) sw[tid] = wc2[((ocg * 8 + (tid >> 4)) * 64 + ci) * 16 + (tid & 15)];
        __syncthreads();

        float pr[5][5];
#pragma unroll
        for (int i = 0; i < 5; i++)
#pragma unroll
            for (int j = 0; j < 5; j++) pr[i][j] = sp[r0 + i][c0 + j];

#pragma unroll
        for (int oc = 0; oc < 8; oc++)
#pragma unroll
            for (int ky = 0; ky < 4; ky++)
#pragma unroll
                for (int kx = 0; kx < 4; kx++) {
                    float wv = sw[oc * 16 + ky * 4 + kx];
#pragma unroll
                    for (int iy = 0; iy < 2; iy++)
#pragma unroll
                        for (int ix = 0; ix < 2; ix++)
                            acc[oc][iy * 2 + ix] = fmaf(pr[ky + iy][kx + ix], wv, acc[oc][iy * 2 + ix]);
                }
    }

    int lane = tid & 31;
#pragma unroll
    for (int oc = 0; oc < 8; oc++) {
        float bias = bc2[ocg * 8 + oc];
        float s = 0.f, sq = 0.f;
#pragma unroll
        for (int iy = 0; iy < 2; iy++)
#pragma unroll
            for (int ix = 0; ix < 2; ix++) {
                int ro = oy + r0 + iy, co = ox + c0 + ix;
                if (ro < OH2 && co < OH2) {
                    float y = acc[oc][iy * 2 + ix] + bias;
                    g_conv2[(((size_t)b * 16 + ocg * 8 + oc) * OH2 + ro) * OH2 + co] = y;
                    s += y; sq += y * y;
                }
            }
#pragma unroll
        for (int off = 16; off > 0; off >>= 1) {
            s  += __shfl_down_sync(0xffffffffu, s,  off);
            sq += __shfl_down_sync(0xffffffffu, sq, off);
        }
        if (lane == 0) { atomicAdd(&ssum[oc], (double)s); atomicAdd(&ssq[oc], (double)sq); }
    }
    __syncthreads();
    if (tid < 8) {
        atomicAdd(&g_c2stats[ocg * 8 + tid],      ssum[tid]);
        atomicAdd(&g_c2stats[16 + ocg * 8 + tid], ssq[tid]);
    }
}

__global__ void pool2_kernel() {
    int t = blockIdx.x * 256 + threadIdx.x;
    if (t >= Bn * 16 * PH2 * PH2) return;
    int j = t % PH2; int tmp = t / PH2;
    int i = tmp % PH2; tmp /= PH2;
    int c = tmp % 16;  int b = tmp / 16;
    float a = g_ab2[c], bt = g_ab2[16 + c];
    size_t base = (((size_t)b * 16 + c) * OH2 + 2 * i) * OH2 + 2 * j;
    float v0 = fmaf(a, g_conv2[base],           bt);
    float v1 = fmaf(a, g_conv2[base + 1],       bt);
    float v2 = fmaf(a, g_conv2[base + OH2],     bt);
    float v3 = fmaf(a, g_conv2[base + OH2 + 1], bt);
    float r = fmaxf(fmaxf(v0, v1), fmaxf(v2, v3));
    g_pool2[t] = fmaxf(r, 0.f);
}

// ---------------- fc1 ----------------
__global__ void fc1_kernel(const float* __restrict__ w, const float* __restrict__ bias) {
    int j = blockIdx.x, b = blockIdx.y, tid = threadIdx.x;
    const float* x  = g_pool2 + (size_t)b * FCIN;
    const float* wr = w + (size_t)j * FCIN;
    float s = 0.f;
    for (int i = tid; i < FCIN; i += 256) s = fmaf(x[i], wr[i], s);
    __shared__ float red[256];
    red[tid] = s;
    __syncthreads();
    for (int k = 128; k > 0; k >>= 1) {
        if (tid < k) red[tid] += red[tid + k];
        __syncthreads();
    }
    if (tid == 0) g_h[b * 32 + j] = red[0] + bias[j];
}

// ---------------- head ----------------
__global__ void head_kernel(const float* __restrict__ gfc, const float* __restrict__ befc,
                            const float* __restrict__ wout, const float* __restrict__ bout,
                            float* __restrict__ out) {
    __shared__ float hn[4][32];
    int t = threadIdx.x;
    if (t < 32) {
        float h0 = g_h[t], h1 = g_h[32 + t], h2 = g_h[64 + t], h3 = g_h[96 + t];
        float m = 0.25f * (h0 + h1 + h2 + h3);
        float d0 = h0 - m, d1 = h1 - m, d2 = h2 - m, d3 = h3 - m;
        float v = 0.25f * (d0 * d0 + d1 * d1 + d2 * d2 + d3 * d3);
        float inv = rsqrtf(v + 1e-5f);
        float gg = gfc[t], bb = befc[t];
        hn[0][t] = tanhf(fmaf(d0 * inv, gg, bb));
        hn[1][t] = tanhf(fmaf(d1 * inv, gg, bb));
        hn[2][t] = tanhf(fmaf(d2 * inv, gg, bb));
        hn[3][t] = tanhf(fmaf(d3 * inv, gg, bb));
    }
    __syncthreads();
    if (t < 12) {
        int b = t / 3, k = t % 3;
        float s = bout[k];
#pragma unroll
        for (int j = 0; j < 32; j++) s = fmaf(hn[b][j], wout[k * 32 + j], s);
        out[b * 3 + k] = s;
    }
}

// ---------------- launch ----------------
extern "C" void kernel_launch(void* const* d_in, const int* in_sizes, int n_in,
                              void* d_out, int out_size) {
    const float* sweep   = (const float*)d_in[0];
    const float* map_pts = (const float*)d_in[1];
    const float* w_pfn_s = (const float*)d_in[2];
    const float* b_pfn_s = (const float*)d_in[3];
    const float* g_pfn_s = (const float*)d_in[4];
    const float* be_pfn_s= (const float*)d_in[5];
    const float* w_pfn_m = (const float*)d_in[6];
    const float* b_pfn_m = (const float*)d_in[7];
    const float* g_pfn_m = (const float*)d_in[8];
    const float* be_pfn_m= (const float*)d_in[9];
    const float* w_c1    = (const float*)d_in[10];
    const float* b_c1    = (const float*)d_in[11];
    const float* g_c1    = (const float*)d_in[12];
    const float* be_c1   = (const float*)d_in[13];
    const float* w_c2    = (const float*)d_in[14];
    const float* b_c2    = (const float*)d_in[15];
    const float* g_c2    = (const float*)d_in[16];
    const float* be_c2   = (const float*)d_in[17];
    const float* w_fc1   = (const float*)d_in[18];
    const float* b_fc1   = (const float*)d_in[19];
    const float* g_fc1   = (const float*)d_in[20];
    const float* be_fc1  = (const float*)d_in[21];
    const float* w_out   = (const float*)d_in[22];
    const float* b_out   = (const float*)d_in[23];
    float* out = (float*)d_out;

    // conv1 buffer -> bias; stats accumulators -> 0
    conv1_init_kernel<<<dim3((OSZ1 + 255) / 256, Bn * 64), 256>>>(b_c1);
    zero_stats_kernel<<<1, 128>>>();

    // PFN moments (both clouds in one launch)
    pfn_mom_kernel<<<dim3(1024, 2), 256>>>(sweep, map_pts);

    // sweep branch: fold -> pfn pass2 (pillar-major features, half 0)
    pfn_fin_kernel<<<1, 64>>>(0, w_pfn_s, b_pfn_s, g_pfn_s, be_pfn_s);
    pfn_max_kernel<<<(Bn * Pn) / 8, 256>>>(sweep, 0);

    // map branch (half 1)
    pfn_fin_kernel<<<1, 64>>>(44, w_pfn_m, b_pfn_m, g_pfn_m, be_pfn_m);
    pfn_max_kernel<<<(Bn * Pn) / 8, 256>>>(map_pts, NPILT);

    // sparse scatter conv1 (both halves), then BN stats pass
    sconv1_kernel<<<dim3(Bn * SC_CHUNKS, 8, 2), 224>>>(w_c1);
    c1stats_kernel<<<Bn * 64, 256>>>();
    bn_fin_kernel<<<1, 64>>>(1, g_c1, be_c1, 1.0 / ((double)Bn * OSZ1));
    pool1_kernel<<<(Bn * 64 * PH1 * PH1 + 255) / 256, 256>>>();

    // conv2 + BN + pool
    conv2_kernel<<<dim3(5, 5, 8), 256>>>(w_c2, b_c2);
    bn_fin_kernel<<<1, 32>>>(2, g_c2, be_c2, 1.0 / ((double)Bn * OH2 * OH2));
    pool2_kernel<<<(Bn * 16 * PH2 * PH2) / 256, 256>>>();

    // fc1 + head
    fc1_kernel<<<dim3(32, 4), 256>>>(w_fc1, b_fc1);
    head_kernel<<<1, 64>>>(g_fc1, be_fc1, w_out, b_out, out);
}

// round 7
// speedup vs baseline: 3.7106x; 1.0837x over previous
#include <cuda_runtime.h>
#include <math.h>

// ---------------- problem constants ----------------
#define Bn     4
#define Pn     12000
#define Nn     32
#define PNn    (Pn*Nn)            // 384000
#define TOTn   (Bn*PNn)           // 1536000
#define HH     282
#define OH1    278
#define PH1    139
#define OH2    136
#define PH2    68
#define FCIN   (16*PH2*PH2)       // 73984
#define NPILT  (Bn*Pn)            // 48000 pillar entries per half
#define OSZ1   (OH1*OH1)          // 77284

typedef unsigned long long ull;

// ---------------- packed f32x2 helpers ----------------
__device__ __forceinline__ ull pk2(float lo, float hi) {
    ull r;
    asm("mov.b64 %0, {%1, %2};" : "=l"(r) : "f"(lo), "f"(hi));
    return r;
}
__device__ __forceinline__ void upk2(ull v, float& lo, float& hi) {
    asm("mov.b64 {%0, %1}, %2;" : "=f"(lo), "=f"(hi) : "l"(v));
}
__device__ __forceinline__ void ffma2(ull& d, ull a, ull b) {
    asm("fma.rn.f32x2 %0, %1, %2, %0;" : "+l"(d) : "l"(a), "l"(b));
}

// ---------------- scratch (static device memory; no allocs) ----------------
__device__ float  g_conv1 [(size_t)Bn*OSZ1*64];       //  79.1 MB, interleaved [b][cell][oc]
__device__ float  g_pool1 [(size_t)Bn*64*PH1*PH1];    //  19.8 MB, planar
__device__ float  g_conv2 [(size_t)Bn*16*OH2*OH2];
__device__ float  g_pool2 [(size_t)Bn*16*PH2*PH2];
__device__ float  g_featT [(size_t)2*NPILT*64];       // pillar-major PFN features
__device__ int    g_cxy   [2*NPILT];                  // packed (cy<<16)|cx per pillar
__device__ double g_mom   [88];
__device__ double g_c1stats[128];
__device__ double g_c2stats[32];
__device__ float  g_weff  [512];
__device__ float  g_beff  [64];
__device__ float  g_ab1   [128];
__device__ float  g_ab2   [32];
__device__ float  g_h     [128];

// ---------------- init ----------------
__global__ void zero_stats_kernel() {
    int t = threadIdx.x;
    if (t < 88)  g_mom[t]     = 0.0;
    if (t < 128) g_c1stats[t] = 0.0;
    if (t < 32)  g_c2stats[t] = 0.0;
}

// conv1 buffer = bias everywhere (interleaved: index & 63 = oc)
__global__ void conv1_init_kernel(const float* __restrict__ bc1) {
    size_t t = (size_t)blockIdx.x * 256 + threadIdx.x;
    if (t >= (size_t)Bn * OSZ1 * 64) return;
    g_conv1[t] = __ldg(bc1 + (t & 63));
}

// ---------------- PFN: raw-input moments ----------------
__global__ void pfn_mom_kernel(const float* __restrict__ xs, const float* __restrict__ xm) {
    const float* x = blockIdx.y ? xm : xs;
    int off = blockIdx.y * 44;
    float a[44];
#pragma unroll
    for (int k = 0; k < 44; k++) a[k] = 0.f;

    for (int i = blockIdx.x * blockDim.x + threadIdx.x; i < TOTn; i += gridDim.x * blockDim.x) {
        int b = i / PNn, r = i % PNn;
        const float* p = x + (size_t)b * 8 * PNn + r;
        float v[8];
#pragma unroll
        for (int c = 0; c < 8; c++) v[c] = p[(size_t)c * PNn];
#pragma unroll
        for (int c = 0; c < 8; c++) a[c] += v[c];
        int k = 8;
#pragma unroll
        for (int c = 0; c < 8; c++)
#pragma unroll
            for (int c2 = c; c2 < 8; c2++)
                a[k++] += v[c] * v[c2];
    }

    __shared__ double sm[44];
    if (threadIdx.x < 44) sm[threadIdx.x] = 0.0;
    __syncthreads();
    int lane = threadIdx.x & 31;
#pragma unroll
    for (int k = 0; k < 44; k++) {
        float s = a[k];
#pragma unroll
        for (int o = 16; o > 0; o >>= 1) s += __shfl_down_sync(0xffffffffu, s, o);
        if (lane == 0) atomicAdd(&sm[k], (double)s);
    }
    __syncthreads();
    if (threadIdx.x < 44) atomicAdd(&g_mom[off + threadIdx.x], sm[threadIdx.x]);
}

// Fold BN(train stats) into effective weight/bias (streaming; no spills).
__global__ void pfn_fin_kernel(int off,
                               const float* __restrict__ w, const float* __restrict__ bias,
                               const float* __restrict__ g, const float* __restrict__ be) {
    int o = threadIdx.x;
    if (o >= 64) return;
    const double invNT = 1.0 / (double)TOTn;

    double wv[8];
#pragma unroll
    for (int c = 0; c < 8; c++) wv[c] = (double)w[o * 8 + c];
    double bo = (double)bias[o];

    double mu = bo;
#pragma unroll
    for (int c = 0; c < 8; c++) mu += wv[c] * (g_mom[off + c] * invNT);

    double quad = 0.0;
    int k = 8;
#pragma unroll
    for (int c = 0; c < 8; c++)
#pragma unroll
        for (int c2 = c; c2 < 8; c2++) {
            double Mv = g_mom[off + k] * invNT;
            k++;
            double t = wv[c] * wv[c2] * Mv;
            quad += (c == c2) ? t : (2.0 * t);
        }

    double ey2 = bo * bo + 2.0 * bo * (mu - bo) + quad;
    double var = ey2 - mu * mu;
    double alpha = (double)g[o] / sqrt(var + 1e-5);
    double beta  = (double)be[o] - mu * alpha;
#pragma unroll
    for (int c = 0; c < 8; c++) g_weff[o * 8 + c] = (float)(alpha * wv[c]);
    g_beff[o] = (float)(alpha * bo + beta);
}

// PFN pass 2: per-(b,p) warp; fused matvec + ReLU + warp-max.
__global__ void pfn_max_kernel(const float* __restrict__ x, int base) {
    __shared__ float swf[512];
    __shared__ float sbf[64];
    int tid = threadIdx.x;
    for (int i = tid; i < 512; i += 256) swf[i] = g_weff[i];
    if (tid < 64) sbf[tid] = g_beff[tid];
    __syncthreads();

    int warp = (blockIdx.x * 256 + tid) >> 5;
    int lane = tid & 31;
    if (warp >= Bn * Pn) return;
    int b = warp / Pn, p = warp % Pn;
    int pe = base + b * Pn + p;

    const float* xb = x + ((size_t)b * 8 * Pn + p) * Nn + lane;
    float xv[8];
#pragma unroll
    for (int c = 0; c < 8; c++) xv[c] = xb[(size_t)c * PNn];

    if (lane == 0) {
        int gx = (int)floorf((xv[0] + 22.0f) / 0.16f);
        int gy = (int)floorf((xv[1] + 22.0f) / 0.16f);
        g_cxy[pe] = (gx << 16) | gy;
    }

    float yk0 = 0.f, yk1 = 0.f;
    for (int o = 0; o < 64; o++) {
        float y = sbf[o];
#pragma unroll
        for (int c = 0; c < 8; c++) y = fmaf(swf[o * 8 + c], xv[c], y);
        y = fmaxf(y, 0.f);
#pragma unroll
        for (int off = 16; off > 0; off >>= 1) y = fmaxf(y, __shfl_xor_sync(0xffffffffu, y, off));
        if (o == lane)      yk0 = y;
        if (o == lane + 32) yk1 = y;
    }
    g_featT[(size_t)pe * 64 + lane]      = yk0;
    g_featT[(size_t)pe * 64 + 32 + lane] = yk1;
}

// ---------------- sparse scatter conv1 (interleaved output, FFMA2, prefetch) ----------------
// block = (chunk of 480 pillars, oc-group of 8, half). thread t<200 = (tap, ocl):
//   t = tap*8 + ocl  -> warp covers 4 taps x 8 consecutive oc -> coalesced REDG (32B runs).
// 64 ci weights register-packed as 32 f32x2 pairs; feature float4s pair naturally.
#define SC_CHUNKS 25
#define SC_PPC    480
#define SC_PB     8             // pillars per staged group (60 groups, ping-pong)
__global__ __launch_bounds__(224) void sconv1_kernel(const float* __restrict__ wc1) {
    __shared__ float sf[2][SC_PB][64];
    __shared__ int   scell[2][SC_PB];
    int t     = threadIdx.x;
    int half  = blockIdx.z;
    int ocg   = blockIdx.y;               // 0..7
    int chunk = blockIdx.x;               // 0..99
    int b     = chunk / SC_CHUNKS;
    int sub   = chunk % SC_CHUNKS;
    int pbase = half * NPILT + b * Pn + sub * SC_PPC;

    int ocl = t & 7;
    int tap = t >> 3;                     // 0..24 for t<200
    int dy  = tap / 5, dx = tap - dy * 5;
    int oc  = ocg * 8 + ocl;

    ull w2[32];
    if (t < 200) {
        const float* wp = wc1 + ((size_t)oc * 128 + half * 64) * 25 + tap;
#pragma unroll
        for (int ci = 0; ci < 64; ci += 2)
            w2[ci >> 1] = pk2(wp[ci * 25], wp[(ci + 1) * 25]);
    }
    float* outp = g_conv1 + (size_t)b * OSZ1 * 64 + oc;

    int lpi = t >> 4, lq = t & 15;        // loader mapping (t < 128)
    float4 pf; int cpf = 0;

    // prologue: stage group 0
    if (t < 128)
        ((float4*)sf[0][lpi])[lq] = ((const float4*)(g_featT + (size_t)(pbase + lpi) * 64))[lq];
    if (t < SC_PB) scell[0][t] = g_cxy[pbase + t];
    __syncthreads();

    for (int gp = 0; gp < SC_PPC / SC_PB; gp++) {
        int cur = gp & 1;

        // prefetch next group into registers
        if (gp + 1 < SC_PPC / SC_PB) {
            int p0 = pbase + (gp + 1) * SC_PB;
            if (t < 128)
                pf = ((const float4*)(g_featT + (size_t)(p0 + lpi) * 64))[lq];
            if (t < SC_PB) cpf = g_cxy[p0 + t];
        }

        if (t < 200) {
#pragma unroll 1
            for (int pi = 0; pi < SC_PB; pi++) {
                const float4* fv = (const float4*)sf[cur][pi];
                ull acc[4] = {0ull, 0ull, 0ull, 0ull};
#pragma unroll
                for (int k = 0; k < 16; k++) {
                    float4 f = fv[k];
                    ffma2(acc[(2 * k) & 3],     pk2(f.x, f.y), w2[2 * k]);
                    ffma2(acc[(2 * k + 1) & 3], pk2(f.z, f.w), w2[2 * k + 1]);
                }
                float a0, a1, a2, a3, a4, a5, a6, a7;
                upk2(acc[0], a0, a1); upk2(acc[1], a2, a3);
                upk2(acc[2], a4, a5); upk2(acc[3], a6, a7);
                float y = ((a0 + a1) + (a2 + a3)) + ((a4 + a5) + (a6 + a7));
                int cxy = scell[cur][pi];
                int oy = (cxy >> 16) - dy;
                int ox = (cxy & 0xFFFF) - dx;
                if ((unsigned)oy < (unsigned)OH1 && (unsigned)ox < (unsigned)OH1)
                    atomicAdd(outp + (size_t)(oy * OH1 + ox) * 64, y);   // coalesced REDG
            }
        }

        // stage prefetched group into the other buffer
        if (gp + 1 < SC_PPC / SC_PB) {
            int nb = 1 - cur;
            if (t < 128) ((float4*)sf[nb][lpi])[lq] = pf;
            if (t < SC_PB) scell[nb][t] = cpf;
        }
        __syncthreads();
    }
}

// conv1 BN statistics (interleaved layout; coalesced oc-minor reads)
#define CSLAB 1936
__global__ void c1stats_kernel() {
    int blk = blockIdx.x;                 // Bn*40
    int b = blk / 40, slab = blk % 40;
    int start = slab * CSLAB;
    int end = start + CSLAB; if (end > OSZ1) end = OSZ1;
    int t = threadIdx.x;
    int oc = t & 63, cg = t >> 6;
    const float* base = g_conv1 + (size_t)b * OSZ1 * 64;
    float s = 0.f, sq = 0.f;
    for (int cell = start + cg; cell < end; cell += 4) {
        float v = base[(size_t)cell * 64 + oc];
        s += v; sq = fmaf(v, v, sq);
    }
    __shared__ float rs[256], rq[256];
    rs[t] = s; rq[t] = sq;
    __syncthreads();
    if (t < 64) {
        double S = (double)rs[t] + (double)rs[t + 64] + (double)rs[t + 128] + (double)rs[t + 192];
        double Q = (double)rq[t] + (double)rq[t + 64] + (double)rq[t + 128] + (double)rq[t + 192];
        atomicAdd(&g_c1stats[oc], S);
        atomicAdd(&g_c1stats[64 + oc], Q);
    }
}

// generic BN finalize -> alpha/beta
__global__ void bn_fin_kernel(int which,
                              const float* __restrict__ g, const float* __restrict__ be,
                              double invN) {
    int C = (which == 1) ? 64 : 16;
    const double* stats = (which == 1) ? g_c1stats : g_c2stats;
    float* ab           = (which == 1) ? g_ab1     : g_ab2;
    int c = threadIdx.x;
    if (c >= C) return;
    double mean = stats[c] * invN;
    double var  = stats[C + c] * invN - mean * mean;
    double alpha = (double)g[c] / sqrt(var + 1e-5);
    double beta  = (double)be[c] - mean * alpha;
    ab[c]     = (float)alpha;
    ab[C + c] = (float)beta;
}

// pool1: interleaved conv1 -> planar pool1 (BN affine + max + ReLU)
__global__ void pool1_kernel() {
    int t = blockIdx.x * 256 + threadIdx.x;
    if (t >= Bn * 64 * PH1 * PH1) return;
    int oc = t & 63;
    int cell = t >> 6;
    int j = cell % PH1; int tmp = cell / PH1;
    int i = tmp % PH1; int b = tmp / PH1;
    float a = g_ab1[oc], bt = g_ab1[64 + oc];
    const float* base = g_conv1 + ((size_t)b * OSZ1 + (size_t)(2 * i) * OH1 + 2 * j) * 64 + oc;
    float v0 = fmaf(a, base[0],             bt);
    float v1 = fmaf(a, base[64],            bt);
    float v2 = fmaf(a, base[(size_t)OH1*64],      bt);
    float v3 = fmaf(a, base[(size_t)(OH1+1)*64],  bt);
    float r = fmaxf(fmaxf(v0, v1), fmaxf(v2, v3));
    g_pool1[(((size_t)b * 64 + oc) * PH1 + i) * PH1 + j] = fmaxf(r, 0.f);
}

// ---------------- conv2: 4x4, 64->16, tile 32x32, 8 oc/block ----------------
__global__ __launch_bounds__(256) void conv2_kernel(const float* __restrict__ wc2,
                                                    const float* __restrict__ bc2) {
    __shared__ float sp[35][36];
    __shared__ float sw[128];
    __shared__ double ssum[8], ssq[8];
    int tid = threadIdx.x;
    int b   = blockIdx.z >> 1, ocg = blockIdx.z & 1;
    int oy  = blockIdx.y * 32, ox = blockIdx.x * 32;
    if (tid < 8) { ssum[tid] = 0.0; ssq[tid] = 0.0; }

    float acc[8][4];
#pragma unroll
    for (int i = 0; i < 8; i++)
#pragma unroll
        for (int j = 0; j < 4; j++) acc[i][j] = 0.f;

    const float* cb = g_pool1 + (size_t)b * 64 * PH1 * PH1;
    int r0 = (tid >> 4) * 2, c0 = (tid & 15) * 2;

    for (int ci = 0; ci < 64; ci++) {
        __syncthreads();
        const float* src = cb + (size_t)ci * PH1 * PH1;
        for (int i = tid; i < 35 * 35; i += 256) {
            int r = i / 35, c = i % 35;
            int gy = oy + r, gx = ox + c;
            sp[r][c] = (gy < PH1 && gx < PH1) ? src[gy * PH1 + gx] : 0.f;
        }
        if (tid < 128) sw[tid] = wc2[((ocg * 8 + (tid >> 4)) * 64 + ci) * 16 + (tid & 15)];
        __syncthreads();

        float pr[5][5];
#pragma unroll
        for (int i = 0; i < 5; i++)
#pragma unroll
            for (int j = 0; j < 5; j++) pr[i][j] = sp[r0 + i][c0 + j];

#pragma unroll
        for (int oc = 0; oc < 8; oc++)
#pragma unroll
            for (int ky = 0; ky < 4; ky++)
#pragma unroll
                for (int kx = 0; kx < 4; kx++) {
                    float wv = sw[oc * 16 + ky * 4 + kx];
#pragma unroll
                    for (int iy = 0; iy < 2; iy++)
#pragma unroll
                        for (int ix = 0; ix < 2; ix++)
                            acc[oc][iy * 2 + ix] = fmaf(pr[ky + iy][kx + ix], wv, acc[oc][iy * 2 + ix]);
                }
    }

    int lane = tid & 31;
#pragma unroll
    for (int oc = 0; oc < 8; oc++) {
        float bias = bc2[ocg * 8 + oc];
        float s = 0.f, sq = 0.f;
#pragma unroll
        for (int iy = 0; iy < 2; iy++)
#pragma unroll
            for (int ix = 0; ix < 2; ix++) {
                int ro = oy + r0 + iy, co = ox + c0 + ix;
                if (ro < OH2 && co < OH2) {
                    float y = acc[oc][iy * 2 + ix] + bias;
                    g_conv2[(((size_t)b * 16 + ocg * 8 + oc) * OH2 + ro) * OH2 + co] = y;
                    s += y; sq += y * y;
                }
            }
#pragma unroll
        for (int off = 16; off > 0; off >>= 1) {
            s  += __shfl_down_sync(0xffffffffu, s,  off);
            sq += __shfl_down_sync(0xffffffffu, sq, off);
        }
        if (lane == 0) { atomicAdd(&ssum[oc], (double)s); atomicAdd(&ssq[oc], (double)sq); }
    }
    __syncthreads();
    if (tid < 8) {
        atomicAdd(&g_c2stats[ocg * 8 + tid],      ssum[tid]);
        atomicAdd(&g_c2stats[16 + ocg * 8 + tid], ssq[tid]);
    }
}

__global__ void pool2_kernel() {
    int t = blockIdx.x * 256 + threadIdx.x;
    if (t >= Bn * 16 * PH2 * PH2) return;
    int j = t % PH2; int tmp = t / PH2;
    int i = tmp % PH2; tmp /= PH2;
    int c = tmp % 16;  int b = tmp / 16;
    float a = g_ab2[c], bt = g_ab2[16 + c];
    size_t base = (((size_t)b * 16 + c) * OH2 + 2 * i) * OH2 + 2 * j;
    float v0 = fmaf(a, g_conv2[base],           bt);
    float v1 = fmaf(a, g_conv2[base + 1],       bt);
    float v2 = fmaf(a, g_conv2[base + OH2],     bt);
    float v3 = fmaf(a, g_conv2[base + OH2 + 1], bt);
    float r = fmaxf(fmaxf(v0, v1), fmaxf(v2, v3));
    g_pool2[t] = fmaxf(r, 0.f);
}

// ---------------- fc1 ----------------
__global__ void fc1_kernel(const float* __restrict__ w, const float* __restrict__ bias) {
    int j = blockIdx.x, b = blockIdx.y, tid = threadIdx.x;
    const float* x  = g_pool2 + (size_t)b * FCIN;
    const float* wr = w + (size_t)j * FCIN;
    float s = 0.f;
    for (int i = tid; i < FCIN; i += 256) s = fmaf(x[i], wr[i], s);
    __shared__ float red[256];
    red[tid] = s;
    __syncthreads();
    for (int k = 128; k > 0; k >>= 1) {
        if (tid < k) red[tid] += red[tid + k];
        __syncthreads();
    }
    if (tid == 0) g_h[b * 32 + j] = red[0] + bias[j];
}

// ---------------- head ----------------
__global__ void head_kernel(const float* __restrict__ gfc, const float* __restrict__ befc,
                            const float* __restrict__ wout, const float* __restrict__ bout,
                            float* __restrict__ out) {
    __shared__ float hn[4][32];
    int t = threadIdx.x;
    if (t < 32) {
        float h0 = g_h[t], h1 = g_h[32 + t], h2 = g_h[64 + t], h3 = g_h[96 + t];
        float m = 0.25f * (h0 + h1 + h2 + h3);
        float d0 = h0 - m, d1 = h1 - m, d2 = h2 - m, d3 = h3 - m;
        float v = 0.25f * (d0 * d0 + d1 * d1 + d2 * d2 + d3 * d3);
        float inv = rsqrtf(v + 1e-5f);
        float gg = gfc[t], bb = befc[t];
        hn[0][t] = tanhf(fmaf(d0 * inv, gg, bb));
        hn[1][t] = tanhf(fmaf(d1 * inv, gg, bb));
        hn[2][t] = tanhf(fmaf(d2 * inv, gg, bb));
        hn[3][t] = tanhf(fmaf(d3 * inv, gg, bb));
    }
    __syncthreads();
    if (t < 12) {
        int b = t / 3, k = t % 3;
        float s = bout[k];
#pragma unroll
        for (int j = 0; j < 32; j++) s = fmaf(hn[b][j], wout[k * 32 + j], s);
        out[b * 3 + k] = s;
    }
}

// ---------------- launch ----------------
extern "C" void kernel_launch(void* const* d_in, const int* in_sizes, int n_in,
                              void* d_out, int out_size) {
    const float* sweep   = (const float*)d_in[0];
    const float* map_pts = (const float*)d_in[1];
    const float* w_pfn_s = (const float*)d_in[2];
    const float* b_pfn_s = (const float*)d_in[3];
    const float* g_pfn_s = (const float*)d_in[4];
    const float* be_pfn_s= (const float*)d_in[5];
    const float* w_pfn_m = (const float*)d_in[6];
    const float* b_pfn_m = (const float*)d_in[7];
    const float* g_pfn_m = (const float*)d_in[8];
    const float* be_pfn_m= (const float*)d_in[9];
    const float* w_c1    = (const float*)d_in[10];
    const float* b_c1    = (const float*)d_in[11];
    const float* g_c1    = (const float*)d_in[12];
    const float* be_c1   = (const float*)d_in[13];
    const float* w_c2    = (const float*)d_in[14];
    const float* b_c2    = (const float*)d_in[15];
    const float* g_c2    = (const float*)d_in[16];
    const float* be_c2   = (const float*)d_in[17];
    const float* w_fc1   = (const float*)d_in[18];
    const float* b_fc1   = (const float*)d_in[19];
    const float* g_fc1   = (const float*)d_in[20];
    const float* be_fc1  = (const float*)d_in[21];
    const float* w_out   = (const float*)d_in[22];
    const float* b_out   = (const float*)d_in[23];
    float* out = (float*)d_out;

    // conv1 buffer -> bias (interleaved); stats -> 0
    {
        size_t n = (size_t)Bn * OSZ1 * 64;
        conv1_init_kernel<<<(int)((n + 255) / 256), 256>>>(b_c1);
    }
    zero_stats_kernel<<<1, 128>>>();

    // PFN moments (both clouds)
    pfn_mom_kernel<<<dim3(1024, 2), 256>>>(sweep, map_pts);

    // sweep branch
    pfn_fin_kernel<<<1, 64>>>(0, w_pfn_s, b_pfn_s, g_pfn_s, be_pfn_s);
    pfn_max_kernel<<<(Bn * Pn) / 8, 256>>>(sweep, 0);

    // map branch
    pfn_fin_kernel<<<1, 64>>>(44, w_pfn_m, b_pfn_m, g_pfn_m, be_pfn_m);
    pfn_max_kernel<<<(Bn * Pn) / 8, 256>>>(map_pts, NPILT);

    // sparse scatter conv1 + stats + BN + pool
    sconv1_kernel<<<dim3(Bn * SC_CHUNKS, 8, 2), 224>>>(w_c1);
    c1stats_kernel<<<Bn * 40, 256>>>();
    bn_fin_kernel<<<1, 64>>>(1, g_c1, be_c1, 1.0 / ((double)Bn * OSZ1));
    pool1_kernel<<<(Bn * 64 * PH1 * PH1 + 255) / 256, 256>>>();

    // conv2 + BN + pool
    conv2_kernel<<<dim3(5, 5, 8), 256>>>(w_c2, b_c2);
    bn_fin_kernel<<<1, 32>>>(2, g_c2, be_c2, 1.0 / ((double)Bn * OH2 * OH2));
    pool2_kernel<<<(Bn * 16 * PH2 * PH2) / 256, 256>>>();

    // fc1 + head
    fc1_kernel<<<dim3(32, 4), 256>>>(w_fc1, b_fc1);
    head_kernel<<<1, 64>>>(g_fc1, be_fc1, w_out, b_out, out);
}